// round 17
// baseline (speedup 1.0000x reference)
#include <cuda_runtime.h>
#include <cuda_fp16.h>
#include <math.h>
#include <stdint.h>

#define D_MODEL 1024
#define N_HEADS 16
#define D_FF    4096
#define BB      2
#define SS      2048
#define DK      64
#define ROWS    (BB*SS)          /* 4096 */
#define LN_EPS  1e-6f

typedef __half  hf;
typedef __half2 hf2;

/* ---------------- scratch (no allocations allowed) ---------------- */
__device__ float g_tmp[ROWS*D_MODEL];
__device__ float g_ao [ROWS*D_MODEL];
__device__ float g_f2 [ROWS*D_MODEL];
__device__ float g_rowsum[(size_t)BB*N_HEADS*SS];

__device__ hf g_x  [ROWS*D_MODEL];
__device__ hf g_wq[D_MODEL*D_MODEL];
__device__ hf g_wk[D_MODEL*D_MODEL];
__device__ hf g_wv[D_MODEL*D_MODEL];
__device__ hf g_wo[D_MODEL*D_MODEL];
__device__ hf g_w1[(size_t)D_MODEL*D_FF];
__device__ hf g_w2[(size_t)D_MODEL*D_FF];
__device__ hf g_q  [ROWS*D_MODEL];
__device__ hf g_k  [ROWS*D_MODEL];
__device__ hf g_vt [ROWS*D_MODEL];
__device__ hf g_c  [ROWS*D_MODEL];
__device__ hf g_ao16[ROWS*D_MODEL];
__device__ hf g_f1 [(size_t)ROWS*D_FF];
__device__ hf g_p  [(size_t)BB*N_HEADS*SS*SS];   /* unnormalized exp, fp16 */

/* ---------------- helpers ---------------- */
__device__ __forceinline__ uint32_t smem_u32(const void* p) {
    uint32_t a;
    asm("{ .reg .u64 t; cvta.to.shared.u64 t, %1; cvt.u32.u64 %0, t; }" : "=r"(a) : "l"(p));
    return a;
}
__device__ __forceinline__ void ldm4(uint32_t* d, uint32_t addr) {
    asm volatile("ldmatrix.sync.aligned.m8n8.x4.shared.b16 {%0,%1,%2,%3}, [%4];"
                 : "=r"(d[0]), "=r"(d[1]), "=r"(d[2]), "=r"(d[3]) : "r"(addr));
}
__device__ __forceinline__ void mma_hf(float* c, const uint32_t* a, uint32_t b0, uint32_t b1) {
    asm volatile("mma.sync.aligned.m16n8k16.row.col.f32.f16.f16.f32 "
                 "{%0,%1,%2,%3}, {%4,%5,%6,%7}, {%8,%9}, {%0,%1,%2,%3};"
                 : "+f"(c[0]), "+f"(c[1]), "+f"(c[2]), "+f"(c[3])
                 : "r"(a[0]), "r"(a[1]), "r"(a[2]), "r"(a[3]), "r"(b0), "r"(b1));
}
#define CP16(dst, src) asm volatile("cp.async.cg.shared.global [%0], [%1], 16;" :: "r"(dst), "l"(src))
#define CPCOMMIT()     asm volatile("cp.async.commit_group;" ::: "memory")
#define CPWAIT(n)      asm volatile("cp.async.wait_group %0;" :: "n"(n) : "memory")

/* ================= fp16 single-pass GEMM (mma.sync) ================= */
#define KSB   80
#define HMAT  (128*KSB)           /* 10240 per matrix */
#define STGB  (2*HMAT)            /* A + B per stage */
#define GEMM_SMEM (3*STGB)        /* 61440 */

template<int OUTM, bool BIAS_ROW, bool RELU>
__global__ void __launch_bounds__(128, 2)
gemm_hf(const hf* __restrict__ A, const hf* __restrict__ B,
        const float* __restrict__ bias,
        float* __restrict__ Cf, hf* __restrict__ Ch,
        float* __restrict__ rowsum,
        int K, int lda, int ldb, int ldc, int HB,
        long long sA0, long long sA1, long long sB0, long long sB1,
        long long sC0, long long sC1, float scale)
{
    extern __shared__ char smem[];
    const uint32_t sb = smem_u32(smem);
    const int tid = threadIdx.x, lane = tid & 31, wid = tid >> 5;

    const int z = blockIdx.z;
    const long long oA = (long long)(z / HB) * sA0 + (long long)(z % HB) * sA1;
    const long long oB = (long long)(z / HB) * sB0 + (long long)(z % HB) * sB1;
    const long long oC = (long long)(z / HB) * sC0 + (long long)(z % HB) * sC1;
    A += oA; B += oB;

    const int row0 = blockIdx.y * 128, col0 = blockIdx.x * 128;
    const int m0 = (wid & 1) * 64, n0 = (wid >> 1) * 64;

    const int r8 = lane & 7, sel = lane >> 3;
    const uint32_t aoff = (uint32_t)(m0 + (sel & 1) * 8 + r8) * KSB + (uint32_t)((sel >> 1) * 8) * 2u;
    const uint32_t boff = (uint32_t)(n0 + (sel >> 1) * 8 + r8) * KSB + (uint32_t)((sel & 1) * 8) * 2u;

    float acc[4][8][4];
#pragma unroll
    for (int i = 0; i < 4; i++)
#pragma unroll
        for (int j = 0; j < 8; j++)
#pragma unroll
            for (int q = 0; q < 4; q++) acc[i][j][q] = 0.f;

    const int NCH = K >> 5;

    auto issue = [&](int it) {
        const int k0 = it * 32;
        const uint32_t s = sb + (uint32_t)(it % 3) * STGB;
#pragma unroll
        for (int i = 0; i < 4; i++) {
            int e = tid + i * 128, r = e >> 2, c = e & 3;
            CP16(s + (uint32_t)(r * KSB + c * 16),
                 A + (long long)(row0 + r) * lda + k0 + c * 8);
        }
#pragma unroll
        for (int i = 0; i < 4; i++) {
            int e = tid + i * 128, r = e >> 2, c = e & 3;
            CP16(s + HMAT + (uint32_t)(r * KSB + c * 16),
                 B + (long long)(col0 + r) * ldb + k0 + c * 8);
        }
        CPCOMMIT();
    };

    issue(0);
    if (NCH > 1) issue(1);
    for (int it = 0; it < NCH; ++it) {
        if (it + 1 < NCH) CPWAIT(1); else CPWAIT(0);
        __syncthreads();
        if (it + 2 < NCH) issue(it + 2);

        const uint32_t stg = sb + (uint32_t)(it % 3) * STGB;
#pragma unroll
        for (int ks = 0; ks < 2; ++ks) {
            uint32_t ah[4][4];
#pragma unroll
            for (int mf = 0; mf < 4; ++mf)
                ldm4(ah[mf], stg + aoff + mf * (16 * KSB) + ks * 32);
#pragma unroll
            for (int p = 0; p < 4; ++p) {
                uint32_t bh[4];
                ldm4(bh, stg + HMAT + boff + p * (16 * KSB) + ks * 32);
#pragma unroll
                for (int mf = 0; mf < 4; ++mf) {
                    mma_hf(acc[mf][2 * p],     ah[mf], bh[0], bh[1]);
                    mma_hf(acc[mf][2 * p + 1], ah[mf], bh[2], bh[3]);
                }
            }
        }
    }

    /* epilogue */
    float* rs = reinterpret_cast<float*>(smem);
    if (OUTM == 2) {
        __syncthreads();
        rs[tid] = 0.f;
        __syncthreads();
    }

    const int g2 = lane >> 2, l2 = lane & 3;
#pragma unroll
    for (int mf = 0; mf < 4; ++mf) {
        const int lr = m0 + mf * 16 + g2;
        const int rg = row0 + lr;
        float p0 = 0.f, p8 = 0.f;
#pragma unroll
        for (int nf = 0; nf < 8; ++nf) {
            const int gn = col0 + n0 + (nf >> 1) * 16 + (nf & 1) * 8 + l2 * 2;
            float c0 = acc[mf][nf][0] * scale, c1 = acc[mf][nf][1] * scale;
            float c2 = acc[mf][nf][2] * scale, c3 = acc[mf][nf][3] * scale;
            if (bias) {
                if (BIAS_ROW) {
                    float b0 = bias[rg], b8 = bias[rg + 8];
                    c0 += b0; c1 += b0; c2 += b8; c3 += b8;
                } else {
                    float b0 = bias[gn], b1 = bias[gn + 1];
                    c0 += b0; c1 += b1; c2 += b0; c3 += b1;
                }
            }
            if (RELU) {
                c0 = fmaxf(c0, 0.f); c1 = fmaxf(c1, 0.f);
                c2 = fmaxf(c2, 0.f); c3 = fmaxf(c3, 0.f);
            }
            const long long i0 = oC + (long long)rg * ldc + gn;
            const long long i8 = oC + (long long)(rg + 8) * ldc + gn;
            if (OUTM == 0) {
                *reinterpret_cast<float2*>(&Cf[i0]) = make_float2(c0, c1);
                *reinterpret_cast<float2*>(&Cf[i8]) = make_float2(c2, c3);
            } else if (OUTM == 4) {
                *reinterpret_cast<hf2*>(&Ch[i0]) = __floats2half2_rn(c0, c1);
                *reinterpret_cast<hf2*>(&Ch[i8]) = __floats2half2_rn(c2, c3);
            } else {  /* OUTM == 2: fp16 exp + fp32 rowsum */
                float e0 = __expf(c0), e1 = __expf(c1);
                float e2 = __expf(c2), e3 = __expf(c3);
                *reinterpret_cast<hf2*>(&Ch[i0]) = __floats2half2_rn(e0, e1);
                *reinterpret_cast<hf2*>(&Ch[i8]) = __floats2half2_rn(e2, e3);
                p0 += e0 + e1; p8 += e2 + e3;
            }
        }
        if (OUTM == 2) {
            atomicAdd(&rs[lr], p0);
            atomicAdd(&rs[lr + 8], p8);
        }
    }
    if (OUTM == 2) {
        __syncthreads();
        atomicAdd(&rowsum[(long long)z * SS + row0 + tid], rs[tid]);
    }
}

/* ============ lean ctx kernel: ctx = (P~ @ V) * inv, no attn write ========
 * A = P16 [SS, SS] fp16 (cp.async direct), B = Vt [DK, ROWS] fp16.
 * Output tile 128 x 64, 4 warps (2m x 2n), warp tile 64x32, 3-stage pipe.
 * Normalization applied in epilogue (per-row scalar).
 */
#define CTXL_A   (128*KSB)             /* 10240 */
#define CTXL_B   (64*KSB)              /* 5120 */
#define CTXL_STG (CTXL_A + CTXL_B)     /* 15360 */
#define CTXL_SMEM (3*CTXL_STG)         /* 46080 */

__global__ void __launch_bounds__(128, 2)
ctx_gemm(const hf* __restrict__ P16, const float* __restrict__ rowsum,
         const hf* __restrict__ Bh, hf* __restrict__ Ch)
{
    extern __shared__ char smem[];
    const uint32_t sb = smem_u32(smem);
    const int tid = threadIdx.x, lane = tid & 31, wid = tid >> 5;
    const int z = blockIdx.y;
    const int row0 = blockIdx.x * 128;

    P16 += (long long)z * SS * SS;
    Bh  += (long long)(z & (N_HEADS - 1)) * DK * ROWS + (long long)(z / N_HEADS) * SS;
    const long long oC = (long long)(z / N_HEADS) * SS * D_MODEL + (long long)(z & (N_HEADS - 1)) * DK;
    const float* rsum = rowsum + (long long)z * SS + row0;

    const int m0 = (wid & 1) * 64, n0 = (wid >> 1) * 32;
    const int r8 = lane & 7, sel = lane >> 3;
    const uint32_t aoff = (uint32_t)(m0 + (sel & 1) * 8 + r8) * KSB + (uint32_t)((sel >> 1) * 8) * 2u;
    const uint32_t boff = (uint32_t)(n0 + (sel >> 1) * 8 + r8) * KSB + (uint32_t)((sel & 1) * 8) * 2u;

    float acc[4][4][4];
#pragma unroll
    for (int i = 0; i < 4; i++)
#pragma unroll
        for (int j = 0; j < 4; j++)
#pragma unroll
            for (int q = 0; q < 4; q++) acc[i][j][q] = 0.f;

    const int NCH = SS / 32;   /* 64 */

    auto issue = [&](int it) {
        const int k0 = it * 32;
        const uint32_t s = sb + (uint32_t)(it % 3) * CTXL_STG;
#pragma unroll
        for (int i = 0; i < 4; i++) {
            int e = tid + i * 128, r = e >> 2, c = e & 3;
            CP16(s + (uint32_t)(r * KSB + c * 16),
                 P16 + (long long)(row0 + r) * SS + k0 + c * 8);
        }
#pragma unroll
        for (int i = 0; i < 2; i++) {
            int e = tid + i * 128, r = e >> 2, c = e & 3;
            CP16(s + CTXL_A + (uint32_t)(r * KSB + c * 16),
                 Bh + (long long)r * ROWS + k0 + c * 8);
        }
        CPCOMMIT();
    };

    issue(0);
    issue(1);
    for (int it = 0; it < NCH; ++it) {
        if (it + 1 < NCH) CPWAIT(1); else CPWAIT(0);
        __syncthreads();
        if (it + 2 < NCH) issue(it + 2);

        const uint32_t stg = sb + (uint32_t)(it % 3) * CTXL_STG;
#pragma unroll
        for (int ks = 0; ks < 2; ++ks) {
            uint32_t ah[4][4];
#pragma unroll
            for (int mf = 0; mf < 4; ++mf)
                ldm4(ah[mf], stg + aoff + mf * (16 * KSB) + ks * 32);
#pragma unroll
            for (int p = 0; p < 2; ++p) {
                uint32_t bh[4];
                ldm4(bh, stg + CTXL_A + boff + p * (16 * KSB) + ks * 32);
#pragma unroll
                for (int mf = 0; mf < 4; ++mf) {
                    mma_hf(acc[mf][2 * p],     ah[mf], bh[0], bh[1]);
                    mma_hf(acc[mf][2 * p + 1], ah[mf], bh[2], bh[3]);
                }
            }
        }
    }

    const int g2 = lane >> 2, l2 = lane & 3;
#pragma unroll
    for (int mf = 0; mf < 4; ++mf) {
        const int lr = m0 + mf * 16 + g2;
        const int rg = row0 + lr;
        const float iv0 = 1.f / rsum[lr], iv8 = 1.f / rsum[lr + 8];
#pragma unroll
        for (int nf = 0; nf < 4; ++nf) {
            const int gcol = n0 + (nf >> 1) * 16 + (nf & 1) * 8 + l2 * 2;
            const long long i0 = oC + (long long)rg * D_MODEL + gcol;
            const long long i8 = oC + (long long)(rg + 8) * D_MODEL + gcol;
            *reinterpret_cast<hf2*>(&Ch[i0]) =
                __floats2half2_rn(acc[mf][nf][0] * iv0, acc[mf][nf][1] * iv0);
            *reinterpret_cast<hf2*>(&Ch[i8]) =
                __floats2half2_rn(acc[mf][nf][2] * iv8, acc[mf][nf][3] * iv8);
        }
    }
}

/* ---------- attn normalize: attn = p16 * inv[row] (streaming) ---------- */
__global__ void norm_kernel(const hf* __restrict__ p16, const float* __restrict__ rowsum,
                            float* __restrict__ attn)
{
    const long long row = blockIdx.x;                 /* 0 .. BB*NH*SS-1 */
    const float inv = 1.f / rowsum[row];
    const hf*  src = p16  + row * SS;
    float*     dst = attn + row * SS;
    const int tid = threadIdx.x;
#pragma unroll
    for (int i = 0; i < 2; i++) {
        int j = (tid + i * 256) * 4;
        uint2 v = *reinterpret_cast<const uint2*>(&src[j]);
        float2 f01 = __half22float2(*reinterpret_cast<hf2*>(&v.x));
        float2 f23 = __half22float2(*reinterpret_cast<hf2*>(&v.y));
        float4 o = make_float4(f01.x * inv, f01.y * inv, f23.x * inv, f23.y * inv);
        *reinterpret_cast<float4*>(&dst[j]) = o;
    }
}

/* ---------- zero rowsum ---------- */
__global__ void zero_kernel(float* __restrict__ p, int n)
{
    int i = blockIdx.x * 256 + threadIdx.x;
    if (i < n) p[i] = 0.f;
}

/* ---------- fp32 -> fp16 ---------- */
__global__ void cvt_kernel(const float* __restrict__ in, hf* __restrict__ o, int n4)
{
    int i = blockIdx.x * 256 + threadIdx.x;
    if (i >= n4) return;
    float4 v = reinterpret_cast<const float4*>(in)[i];
    hf2 h01 = __floats2half2_rn(v.x, v.y);
    hf2 h23 = __floats2half2_rn(v.z, v.w);
    uint2 h;
    h.x = *reinterpret_cast<uint32_t*>(&h01);
    h.y = *reinterpret_cast<uint32_t*>(&h23);
    reinterpret_cast<uint2*>(o)[i] = h;
}

/* ---------- W[Kdim,Ndim] -> Wt fp16 [Ndim,Kdim] ---------- */
__global__ void splitT_kernel(const float* __restrict__ W, hf* __restrict__ t16,
                              int Kdim, int Ndim)
{
    __shared__ float t[32][33];
    const int n0 = blockIdx.x * 32, k0 = blockIdx.y * 32;
    const int tx = threadIdx.x, ty = threadIdx.y;
#pragma unroll
    for (int i = 0; i < 32; i += 8)
        t[ty + i][tx] = W[(long long)(k0 + ty + i) * Ndim + n0 + tx];
    __syncthreads();
#pragma unroll
    for (int i = 0; i < 32; i += 8)
        t16[(long long)(n0 + ty + i) * Kdim + k0 + tx] = __float2half_rn(t[tx][ty + i]);
}

/* ------------- out = alpha*(v-mean)/(std+eps)+beta, v = x+y ------------- */
__global__ void add_ln_kernel(const float* __restrict__ x, const float* __restrict__ y,
                              const float* __restrict__ alpha, const float* __restrict__ beta,
                              float* __restrict__ out, hf* __restrict__ o16)
{
    __shared__ float v[D_MODEL];
    __shared__ float red[256];
    const int tid = threadIdx.x;
    const long long base = (long long)blockIdx.x * D_MODEL;

    float s = 0.f;
    for (int j = tid; j < D_MODEL; j += 256) {
        float t = x[base + j] + y[base + j];
        v[j] = t;
        s += t;
    }
    red[tid] = s; __syncthreads();
    for (int st = 128; st > 0; st >>= 1) {
        if (tid < st) red[tid] += red[tid + st];
        __syncthreads();
    }
    const float m = red[0] * (1.f / D_MODEL);
    __syncthreads();

    float c2 = 0.f;
    for (int j = tid; j < D_MODEL; j += 256) {
        float c = v[j] - m;
        c2 += c * c;
    }
    red[tid] = c2; __syncthreads();
    for (int st = 128; st > 0; st >>= 1) {
        if (tid < st) red[tid] += red[tid + st];
        __syncthreads();
    }
    const float stdv = sqrtf(red[0] / (float)(D_MODEL - 1));
    const float inv  = 1.f / (stdv + LN_EPS);
    for (int j = tid * 2; j < D_MODEL; j += 512) {
        float o0 = alpha[j] * (v[j] - m) * inv + beta[j];
        float o1 = alpha[j + 1] * (v[j + 1] - m) * inv + beta[j + 1];
        *reinterpret_cast<float2*>(&out[base + j]) = make_float2(o0, o1);
        if (o16)
            *reinterpret_cast<hf2*>(&o16[base + j]) = __floats2half2_rn(o0, o1);
    }
}

/* ---------------- host dispatch ---------------- */
template<int OUTM, bool BIAS_ROW, bool RELU>
static void run_g(const hf* A, const hf* B,
                  const float* bias, float* Cf, hf* Ch, float* rowsum,
                  int M, int N, int K, int lda, int ldb, int ldc,
                  int batch, int HB,
                  long long sA0, long long sA1, long long sB0, long long sB1,
                  long long sC0, long long sC1, float scale)
{
    cudaFuncSetAttribute((const void*)gemm_hf<OUTM, BIAS_ROW, RELU>,
                         cudaFuncAttributeMaxDynamicSharedMemorySize, GEMM_SMEM);
    dim3 grid(N / 128, M / 128, batch);
    gemm_hf<OUTM, BIAS_ROW, RELU><<<grid, 128, GEMM_SMEM>>>(
        A, B, bias, Cf, Ch, rowsum, K, lda, ldb, ldc,
        HB, sA0, sA1, sB0, sB1, sC0, sC1, scale);
}

#define GETSYM(var, sym) cudaGetSymbolAddress((void**)&var, sym)

extern "C" void kernel_launch(void* const* d_in, const int* in_sizes, int n_in,
                              void* d_out, int out_size)
{
    const float* x   = (const float*)d_in[0];
    const float* Wq  = (const float*)d_in[1];
    const float* bq  = (const float*)d_in[2];
    const float* Wk  = (const float*)d_in[3];
    const float* bk  = (const float*)d_in[4];
    const float* Wv  = (const float*)d_in[5];
    const float* bv  = (const float*)d_in[6];
    const float* Wo  = (const float*)d_in[7];
    const float* bo  = (const float*)d_in[8];
    const float* W1  = (const float*)d_in[9];
    const float* b1  = (const float*)d_in[10];
    const float* W2  = (const float*)d_in[11];
    const float* b2  = (const float*)d_in[12];
    const float* a1  = (const float*)d_in[13];
    const float* be1 = (const float*)d_in[14];
    const float* a2  = (const float*)d_in[15];
    const float* be2 = (const float*)d_in[16];

    float* out  = (float*)d_out;
    float* enc  = out;
    float* attn = out + (size_t)ROWS * D_MODEL;

    static cudaStream_t s_aux = nullptr;
    static cudaEvent_t ev_fork = nullptr, ev_join = nullptr;
    if (!s_aux) {
        cudaStreamCreateWithFlags(&s_aux, cudaStreamNonBlocking);
        cudaEventCreateWithFlags(&ev_fork, cudaEventDisableTiming);
        cudaEventCreateWithFlags(&ev_join, cudaEventDisableTiming);
    }

    float *TMP, *AO, *F2, *RS;
    GETSYM(TMP, g_tmp); GETSYM(AO, g_ao); GETSYM(F2, g_f2); GETSYM(RS, g_rowsum);
    hf *x16, *wq, *wk, *wv, *wo, *w1, *w2;
    hf *qq, *kk, *vt, *cc, *ao16, *f1, *pp;
    GETSYM(x16, g_x);
    GETSYM(wq, g_wq); GETSYM(wk, g_wk); GETSYM(wv, g_wv); GETSYM(wo, g_wo);
    GETSYM(w1, g_w1); GETSYM(w2, g_w2);
    GETSYM(qq, g_q); GETSYM(kk, g_k); GETSYM(vt, g_vt); GETSYM(cc, g_c);
    GETSYM(ao16, g_ao16); GETSYM(f1, g_f1); GETSYM(pp, g_p);

    const long long sBD = (long long)SS * D_MODEL;
    const long long sSS = (long long)SS * SS;
    dim3 tb(32, 8);

    /* 0 */ cvt_kernel<<<(ROWS * D_MODEL / 4 + 255) / 256, 256>>>(x, x16, ROWS * D_MODEL / 4);
    /* 1 */ splitT_kernel<<<dim3(D_MODEL / 32, D_MODEL / 32), tb>>>(Wq, wq, D_MODEL, D_MODEL);
    /* 2 */ splitT_kernel<<<dim3(D_MODEL / 32, D_MODEL / 32), tb>>>(Wk, wk, D_MODEL, D_MODEL);
    /* 3: Q = x @ Wq^T */
    run_g<4, false, false>(x16, wq, bq, nullptr, qq, nullptr,
                           ROWS, D_MODEL, D_MODEL, D_MODEL, D_MODEL, D_MODEL,
                           1, 1, 0, 0, 0, 0, 0, 0, 1.f);
    /* 4 */ zero_kernel<<<(BB * N_HEADS * SS + 255) / 256, 256>>>(RS, BB * N_HEADS * SS);
    /* 5: K = x @ Wk^T   <- ncu capture */
    run_g<4, false, false>(x16, wk, bk, nullptr, kk, nullptr,
                           ROWS, D_MODEL, D_MODEL, D_MODEL, D_MODEL, D_MODEL,
                           1, 1, 0, 0, 0, 0, 0, 0, 1.f);
    /* 6 */ splitT_kernel<<<dim3(D_MODEL / 32, D_MODEL / 32), tb>>>(Wv, wv, D_MODEL, D_MODEL);
    /* 7: Vt = Wv^T @ x^T (row bias) */
    run_g<4, true, false>(wv, x16, bv, nullptr, vt, nullptr,
                          D_MODEL, ROWS, D_MODEL, D_MODEL, D_MODEL, ROWS,
                          1, 1, 0, 0, 0, 0, 0, 0, 1.f);
    /* 8: P~ = exp(QK^T/8) fp16 -> g_p + rowsums */
    run_g<2, false, false>(qq, kk, nullptr, nullptr, pp, RS,
                           SS, SS, DK, D_MODEL, D_MODEL, SS,
                           BB * N_HEADS, N_HEADS,
                           sBD, DK, sBD, DK,
                           (long long)N_HEADS * sSS, sSS, 0.125f);

    /* fork: attn normalization runs on side stream, hidden under FFN */
    cudaEventRecord(ev_fork, 0);
    cudaStreamWaitEvent(s_aux, ev_fork, 0);
    norm_kernel<<<BB * N_HEADS * SS, 256, 0, s_aux>>>(pp, RS, attn);
    cudaEventRecord(ev_join, s_aux);

    /* 9: ctx = (P~ @ V) * inv (lean) */
    {
        cudaFuncSetAttribute((const void*)ctx_gemm,
                             cudaFuncAttributeMaxDynamicSharedMemorySize, CTXL_SMEM);
        dim3 grid(SS / 128, BB * N_HEADS);
        ctx_gemm<<<grid, 128, CTXL_SMEM>>>(pp, RS, vt, cc);
    }
    /* 10 */ splitT_kernel<<<dim3(D_MODEL / 32, D_MODEL / 32), tb>>>(Wo, wo, D_MODEL, D_MODEL);
    /* 11: proj = ctx @ Wo + bo */
    run_g<0, false, false>(cc, wo, bo, TMP, nullptr, nullptr,
                           ROWS, D_MODEL, D_MODEL, D_MODEL, D_MODEL, D_MODEL,
                           1, 1, 0, 0, 0, 0, 0, 0, 1.f);
    /* 12: AO = LN(x + proj) */
    add_ln_kernel<<<ROWS, 256>>>(x, TMP, a1, be1, AO, ao16);
    /* 13 */ splitT_kernel<<<dim3(D_FF / 32, D_MODEL / 32), tb>>>(W1, w1, D_MODEL, D_FF);
    /* 14: F1 = relu(AO @ W1 + b1) */
    run_g<4, false, true>(ao16, w1, b1, nullptr, f1, nullptr,
                          ROWS, D_FF, D_MODEL, D_MODEL, D_MODEL, D_FF,
                          1, 1, 0, 0, 0, 0, 0, 0, 1.f);
    /* 15 */ splitT_kernel<<<dim3(D_MODEL / 32, D_FF / 32), tb>>>(W2, w2, D_FF, D_MODEL);
    /* 16: ff2 = F1 @ W2 + b2 */
    run_g<0, false, false>(f1, w2, b2, F2, nullptr, nullptr,
                           ROWS, D_MODEL, D_FF, D_FF, D_FF, D_MODEL,
                           1, 1, 0, 0, 0, 0, 0, 0, 1.f);
    /* 17: enc = LN(AO + ff2) */
    add_ln_kernel<<<ROWS, 256>>>(AO, F2, a2, be2, enc, nullptr);

    /* join: attn write must complete before kernel_launch's work is done */
    cudaStreamWaitEvent(0, ev_join, 0);

    (void)in_sizes; (void)n_in; (void)out_size;
}